// round 12
// baseline (speedup 1.0000x reference)
#include <cuda_runtime.h>

#define NMAX 50176
#define EMAX 800064
#define FEAT 32
#define HID  64

typedef unsigned long long ull;

// ---------------- scratch (device globals; no allocation allowed) ----------
__device__ __align__(16)  float g_do_inv[NMAX];
__device__ __align__(16)  float g_di_inv[NMAX];
__device__ __align__(16)  float g_dis[NMAX];
__device__ __align__(16)  int   g_ccnt[NMAX];
__device__ __align__(16)  int   g_rcnt[NMAX];
__device__ __align__(16)  int   g_coff[NMAX + 1];
__device__ __align__(16)  int   g_roff[NMAX + 1];
__device__ __align__(16)  int   g_ccur[NMAX];
__device__ __align__(16)  int   g_rcur[NMAX];
__device__ __align__(16)  ull   g_cpay[EMAX];   // (f32 weight_out bits << 32) | src row r
__device__ __align__(16)  ull   g_rpay[EMAX];   // (f32 weight_in  bits << 32) | src col c
__device__ __align__(128) float g_P1o[NMAX * FEAT];
__device__ __align__(128) float g_P1i[NMAX * FEAT];
__device__ __align__(128) float g_P2o[NMAX * FEAT];
__device__ __align__(128) float g_P2i[NMAX * FEAT];
__device__ __align__(256) float g_H[NMAX * HID];
__device__ __align__(256) float g_xw[NMAX * HID];
__device__ __align__(256) float g_y[NMAX * HID];
__device__ __align__(16)  float g_Wcat[160 * 128];
__device__ __align__(16)  float g_bcat[128];
__device__ float g_S[HID];
__device__ float g_SS[HID];

// ---------------- helpers ----------------
__device__ __forceinline__ float sigm(float z) { return 1.0f / (1.0f + expf(-z)); }

__device__ __forceinline__ ull pk(float lo, float hi) {
    ull r; asm("mov.b64 %0, {%1, %2};" : "=l"(r) : "f"(lo), "f"(hi)); return r;
}
__device__ __forceinline__ float2 upk(ull v) {
    float2 r; asm("mov.b64 {%0, %1}, %2;" : "=f"(r.x), "=f"(r.y) : "l"(v)); return r;
}
__device__ __forceinline__ void fma2(ull& d, ull a, ull b) {
    asm("fma.rn.f32x2 %0, %1, %2, %0;" : "+l"(d) : "l"(a), "l"(b));
}

// ---------------- kernels ----------------

// zero atomic targets + stats + build fused 160x128 gate weight (one launch)
__global__ void k_init(const float* __restrict__ Wz, const float* __restrict__ Wh,
                       const float* __restrict__ bz, const float* __restrict__ bh, int n) {
    int i = blockIdx.x * blockDim.x + threadIdx.x;
    if (i < n) {
        g_do_inv[i] = 0.f; g_di_inv[i] = 0.f;
        g_ccnt[i] = 0; g_rcnt[i] = 0;
    }
    if (i < HID) { g_S[i] = 0.f; g_SS[i] = 0.f; }
    if (i < 160 * 128) {
        int k5 = i >> 7;
        int j  = i & 127;
        int b = k5 >> 5;
        int f = k5 & 31;
        const float* Wg = (j < 64) ? Wz : Wh;
        int jj = j & 63;
        float v;
        if (b == 0) {
            v = Wg[((0 * 3 + 0) * 96 + f) * 64 + jj] + Wg[((1 * 3 + 0) * 96 + f) * 64 + jj];
        } else {
            int d = (b <= 2) ? 0 : 1;
            int k = (b <= 2) ? b : (b - 2);
            v = Wg[((d * 3 + k) * 96 + f) * 64 + jj];
        }
        g_Wcat[i] = v;
    } else if (i < 160 * 128 + 128) {
        int j = i - 160 * 128;
        g_bcat[j] = (j < 64) ? bz[j] : bh[j - 64];
    }
}

// weighted degrees + CSR bin counts
__global__ void k_deg(const int* __restrict__ row, const int* __restrict__ col,
                      const float* __restrict__ ew, int E) {
    int e = blockIdx.x * blockDim.x + threadIdx.x;
    if (e >= E) return;
    int r = row[e], c = col[e];
    float w = ew[e];
    atomicAdd(&g_do_inv[r], w);
    atomicAdd(&g_di_inv[c], w);
    atomicAdd(&g_ccnt[c], 1);
    atomicAdd(&g_rcnt[r], 1);
}

// single-phase offsets: each block sums all preceding raw counts for its base
// (~25k ints avg, block-parallel), then per-tile inclusive scan -> off/cur.
// Col-array blocks also fold in the degree-inverse / dis computation.
// grid = 2*NB; blocks [0,NB) -> ccnt/coff, [NB,2NB) -> rcnt/roff.
__global__ void __launch_bounds__(256) k_off(int n, int NB) {
    int arr = (blockIdx.x >= NB) ? 1 : 0;
    int b = blockIdx.x - arr * NB;
    const int* cnt = arr ? g_rcnt : g_ccnt;
    int* off = arr ? g_roff : g_coff;
    int* cur = arr ? g_rcur : g_ccur;
    int t = threadIdx.x;
    int i = b * 256 + t;

    if (arr == 0 && i < n) {
        float a = g_do_inv[i];
        g_do_inv[i] = (a > 0.f) ? (1.0f / a) : 0.f;
        float d = g_di_inv[i];
        g_di_inv[i] = (d > 0.f) ? (1.0f / d) : 0.f;
        g_dis[i] = rsqrtf((float)g_ccnt[i] + 1.0f);
    }

    // base = sum cnt[0 .. b*256)
    int lim = b * 256;
    int part = 0;
    for (int q = t; q < lim; q += 256) part += cnt[q];
#pragma unroll
    for (int o = 16; o > 0; o >>= 1) part += __shfl_down_sync(0xffffffffu, part, o);
    __shared__ int wred[8];
    if ((t & 31) == 0) wred[t >> 5] = part;
    __syncthreads();
    __shared__ int sbase;
    if (t == 0) {
        int s = 0;
#pragma unroll
        for (int q = 0; q < 8; q++) s += wred[q];
        sbase = s;
    }
    // per-tile inclusive scan
    __shared__ int sm[256];
    int v = (i < n) ? cnt[i] : 0;
    sm[t] = v;
    __syncthreads();
    for (int o = 1; o < 256; o <<= 1) {
        int u = (t >= o) ? sm[t - o] : 0;
        __syncthreads();
        sm[t] += u;
        __syncthreads();
    }
    int excl = sbase + sm[t] - v;
    if (i < n) { off[i] = excl; cur[i] = excl; }
    if (i == n - 1) off[n] = excl + v;
}

// place each edge payload into its dest bin (order within bin irrelevant)
__global__ void k_fill(const int* __restrict__ row, const int* __restrict__ col,
                       const float* __restrict__ ew, int E) {
    int e = blockIdx.x * blockDim.x + threadIdx.x;
    if (e >= E) return;
    int r = row[e], c = col[e];
    float w = ew[e];
    float wo = w * g_do_inv[r];
    float wi = w * g_di_inv[c];
    int p = atomicAdd(&g_ccur[c], 1);
    g_cpay[p] = ((ull)__float_as_uint(wo) << 32) | (unsigned)r;
    int p2 = atomicAdd(&g_rcur[r], 1);
    g_rpay[p2] = ((ull)__float_as_uint(wi) << 32) | (unsigned)c;
}

// diffusion hop as atomic-free gather, software-pipelined 4 edges/iteration.
// warp per (node,dir); lane = feature.
__global__ void k_spmm_g(const float* __restrict__ x, int hop, int n) {
    int t = blockIdx.x * blockDim.x + threadIdx.x;
    int wg = t >> 5;
    int lane = t & 31;
    if (wg >= 2 * n) return;
    int node = wg >> 1;
    int dir = wg & 1;
    const float* src;
    float* dst;
    const ull* pay;
    const int* off;
    if (dir == 0) { src = (hop == 1) ? x : g_P1o; dst = (hop == 1) ? g_P1o : g_P2o; pay = g_cpay; off = g_coff; }
    else          { src = (hop == 1) ? x : g_P1i; dst = (hop == 1) ? g_P1i : g_P2i; pay = g_rpay; off = g_roff; }
    int b0 = off[node], b1 = off[node + 1];
    float acc = 0.f;
    int i = b0;
    for (; i + 4 <= b1; i += 4) {
        ull p0 = pay[i];
        ull p1 = pay[i + 1];
        ull p2 = pay[i + 2];
        ull p3 = pay[i + 3];
        int s0 = (int)(unsigned)(p0 & 0xffffffffu);
        int s1 = (int)(unsigned)(p1 & 0xffffffffu);
        int s2 = (int)(unsigned)(p2 & 0xffffffffu);
        int s3 = (int)(unsigned)(p3 & 0xffffffffu);
        float v0 = src[s0 * FEAT + lane];
        float v1 = src[s1 * FEAT + lane];
        float v2 = src[s2 * FEAT + lane];
        float v3 = src[s3 * FEAT + lane];
        acc = fmaf(__uint_as_float((unsigned)(p0 >> 32)), v0, acc);
        acc = fmaf(__uint_as_float((unsigned)(p1 >> 32)), v1, acc);
        acc = fmaf(__uint_as_float((unsigned)(p2 >> 32)), v2, acc);
        acc = fmaf(__uint_as_float((unsigned)(p3 >> 32)), v3, acc);
    }
    for (; i < b1; i++) {
        ull p = pay[i];
        int s = (int)(unsigned)(p & 0xffffffffu);
        acc = fmaf(__uint_as_float((unsigned)(p >> 32)), src[s * FEAT + lane], acc);
    }
    dst[node * FEAT + lane] = acc;
}

// fused gate GEMM (f32x2): [x|P1o|P2o|P1i|P2i](Nx160) @ Wcat(160x128)+bcat,
// H = (1-sigmoid(Zd))*tanh(Hd); gate halves exchanged via shfl_xor(16).
__global__ void __launch_bounds__(128) k_gates(const float* __restrict__ x, int n) {
    __shared__ ull p2s[32 * 160];  // 40 KB
    int tid = threadIdx.x;
    int n0 = blockIdx.x * 32;

    for (int idx = tid; idx < 32 * 160; idx += 128) {
        int m = idx / 160;
        int k = idx - m * 160;
        int node = n0 + m;
        float v = 0.f;
        if (node < n) {
            int b = k >> 5, f = k & 31;
            const float* src = (b == 0) ? x : (b == 1) ? g_P1o : (b == 2) ? g_P2o
                             : (b == 3) ? g_P1i : g_P2i;
            v = src[node * FEAT + f];
        }
        p2s[idx] = pk(v, v);
    }
    __syncthreads();

    int w = tid >> 5, j = tid & 31;
    int m0 = w * 8;

    ull acc[8][2];
    float4 bv = *reinterpret_cast<const float4*>(&g_bcat[4 * j]);
    ull b01 = pk(bv.x, bv.y), b23 = pk(bv.z, bv.w);
#pragma unroll
    for (int m = 0; m < 8; m++) { acc[m][0] = b01; acc[m][1] = b23; }

    const ulonglong2* Wm = reinterpret_cast<const ulonglong2*>(g_Wcat);
    for (int k = 0; k < 160; k++) {
        ulonglong2 wv = Wm[k * 32 + j];
#pragma unroll
        for (int m = 0; m < 8; m++) {
            ull pv = p2s[(m0 + m) * 160 + k];
            fma2(acc[m][0], wv.x, pv);
            fma2(acc[m][1], wv.y, pv);
        }
    }

#pragma unroll
    for (int m = 0; m < 8; m++) {
        int node = n0 + m0 + m;
        float2 a0 = upk(acc[m][0]);
        float2 a1 = upk(acc[m][1]);
        float p0 = __shfl_xor_sync(0xffffffffu, a0.x, 16);
        float p1 = __shfl_xor_sync(0xffffffffu, a0.y, 16);
        float p2 = __shfl_xor_sync(0xffffffffu, a1.x, 16);
        float p3 = __shfl_xor_sync(0xffffffffu, a1.y, 16);
        if (j < 16 && node < n) {
            float4 h;
            h.x = (1.f - sigm(a0.x)) * tanhf(p0);
            h.y = (1.f - sigm(a0.y)) * tanhf(p1);
            h.z = (1.f - sigm(a1.x)) * tanhf(p2);
            h.w = (1.f - sigm(a1.y)) * tanhf(p3);
            *reinterpret_cast<float4*>(&g_H[node * HID + 4 * j]) = h;
        }
    }
}

// xw = H @ gcn_w (f32x2). Self-term/bias handled in k_gcn_gs.
__global__ void __launch_bounds__(128) k_xw(const float* __restrict__ gcn_w, int n) {
    __shared__ ull h2s[32 * 64];
    int tid = threadIdx.x;
    int n0 = blockIdx.x * 32;

    for (int idx = tid; idx < 32 * 64; idx += 128) {
        int m = idx >> 6, k = idx & 63;
        int node = n0 + m;
        float v = (node < n) ? g_H[node * HID + k] : 0.f;
        h2s[idx] = pk(v, v);
    }
    __syncthreads();

    int w = tid >> 5, j = tid & 31;
    int m0 = w * 8;

    ull acc[8];
#pragma unroll
    for (int m = 0; m < 8; m++) acc[m] = 0ull;

    for (int k = 0; k < 64; k++) {
        ull wv = *reinterpret_cast<const ull*>(&gcn_w[k * 64 + 2 * j]);
#pragma unroll
        for (int m = 0; m < 8; m++) {
            fma2(acc[m], wv, h2s[(m0 + m) * 64 + k]);
        }
    }

#pragma unroll
    for (int m = 0; m < 8; m++) {
        int node = n0 + m0 + m;
        if (node < n) {
            float2 a = upk(acc[m]);
            *reinterpret_cast<float2*>(&g_xw[node * HID + 2 * j]) = a;
        }
    }
}

// GCN gather + fused BN statistics. warp per node c; lane = channels lane, lane+32.
// y[c] = dis[c]^2*xw[c] + gcn_b + sum_in dis[r]*dis[c]*xw[r]; block accumulates
// relu sums / sumsq in smem, one global atomic per channel per block.
__global__ void __launch_bounds__(256) k_gcn_gs(const float* __restrict__ gcn_b, int n) {
    __shared__ float s1[64], s2[64];
    int tid = threadIdx.x;
    if (tid < 64) { s1[tid] = 0.f; s2[tid] = 0.f; }
    __syncthreads();

    int t = blockIdx.x * blockDim.x + tid;
    int c = t >> 5;
    int lane = t & 31;
    if (c < n) {
        float dc = g_dis[c];
        float d2 = dc * dc;
        float a0 = fmaf(d2, g_xw[c * HID + lane],      gcn_b[lane]);
        float a1 = fmaf(d2, g_xw[c * HID + lane + 32], gcn_b[lane + 32]);
        int b0 = g_coff[c], b1 = g_coff[c + 1];
        int i = b0;
        for (; i + 2 <= b1; i += 2) {
            ull p0 = g_cpay[i];
            ull p1 = g_cpay[i + 1];
            int r0 = (int)(unsigned)(p0 & 0xffffffffu);
            int r1 = (int)(unsigned)(p1 & 0xffffffffu);
            float n0 = g_dis[r0] * dc;
            float n1 = g_dis[r1] * dc;
            float u00 = g_xw[r0 * HID + lane];
            float u01 = g_xw[r0 * HID + lane + 32];
            float u10 = g_xw[r1 * HID + lane];
            float u11 = g_xw[r1 * HID + lane + 32];
            a0 = fmaf(n0, u00, a0);
            a1 = fmaf(n0, u01, a1);
            a0 = fmaf(n1, u10, a0);
            a1 = fmaf(n1, u11, a1);
        }
        for (; i < b1; i++) {
            ull p = g_cpay[i];
            int r = (int)(unsigned)(p & 0xffffffffu);
            float nrm = g_dis[r] * dc;
            a0 = fmaf(nrm, g_xw[r * HID + lane],      a0);
            a1 = fmaf(nrm, g_xw[r * HID + lane + 32], a1);
        }
        g_y[c * HID + lane]      = a0;
        g_y[c * HID + lane + 32] = a1;
        float r0 = fmaxf(a0, 0.f), r1 = fmaxf(a1, 0.f);
        atomicAdd(&s1[lane],      r0);
        atomicAdd(&s2[lane],      r0 * r0);
        atomicAdd(&s1[lane + 32], r1);
        atomicAdd(&s2[lane + 32], r1 * r1);
    }
    __syncthreads();
    if (tid < 64) {
        atomicAdd(&g_S[tid],  s1[tid]);
        atomicAdd(&g_SS[tid], s2[tid]);
    }
}

// out[n] = dot(relu(y[n,:]), coef) + cnst, BN+linear fold computed inline.
__global__ void k_out(const float* __restrict__ gamma, const float* __restrict__ beta,
                      const float* __restrict__ lw, const float* __restrict__ lb,
                      float* __restrict__ out, int n) {
    int t = blockIdx.x * blockDim.x + threadIdx.x;
    int node = t >> 5;
    int j = t & 31;
    if (node >= n) return;
    float invn = 1.0f / (float)n;
    int j1 = j + 32;
    float m0 = g_S[j]  * invn,            m1 = g_S[j1] * invn;
    float v0 = g_SS[j] * invn - m0 * m0,  v1 = g_SS[j1] * invn - m1 * m1;
    float a0 = gamma[j]  * rsqrtf(v0 + 1e-5f);
    float a1 = gamma[j1] * rsqrtf(v1 + 1e-5f);
    float w0 = lw[j], w1 = lw[j1];
    float c0 = a0 * w0, c1 = a1 * w1;
    float part = (beta[j] - m0 * a0) * w0 + (beta[j1] - m1 * a1) * w1;
    float acc = fmaxf(g_y[node * HID + j],  0.f) * c0
              + fmaxf(g_y[node * HID + j1], 0.f) * c1
              + part;
#pragma unroll
    for (int o = 16; o > 0; o >>= 1) acc += __shfl_down_sync(0xffffffffu, acc, o);
    if (j == 0) out[node] = acc + lb[0];
}

// ---------------- launch ----------------
extern "C" void kernel_launch(void* const* d_in, const int* in_sizes, int n_in,
                              void* d_out, int out_size) {
    const float* x     = (const float*)d_in[0];
    const int*   ei    = (const int*)d_in[1];
    const float* ew    = (const float*)d_in[2];
    const float* Wz    = (const float*)d_in[3];
    const float* bz    = (const float*)d_in[4];
    const float* Wh    = (const float*)d_in[7];
    const float* bh    = (const float*)d_in[8];
    const float* gcn_w = (const float*)d_in[9];
    const float* gcn_b = (const float*)d_in[10];
    const float* gamma = (const float*)d_in[11];
    const float* beta  = (const float*)d_in[12];
    const float* lw    = (const float*)d_in[13];
    const float* lb    = (const float*)d_in[14];
    float* out = (float*)d_out;

    int n = in_sizes[0] / FEAT;
    int E = in_sizes[2];
    const int* row = ei;
    const int* col = ei + E;
    int NB = (n + 255) / 256;

    k_init<<<(n + 255) / 256, 256>>>(Wz, Wh, bz, bh, n);
    k_deg<<<(E + 255) / 256, 256>>>(row, col, ew, E);
    k_off<<<2 * NB, 256>>>(n, NB);     // offsets + cursors + degree-inverse
    k_fill<<<(E + 255) / 256, 256>>>(row, col, ew, E);
    // hop 1 (both dirs), hop 2 (both dirs) — pipelined atomic-free gathers
    k_spmm_g<<<(2 * n * 32 + 255) / 256, 256>>>(x, 1, n);
    k_spmm_g<<<(2 * n * 32 + 255) / 256, 256>>>(x, 2, n);
    // fused gates -> H
    k_gates<<<(n + 31) / 32, 128>>>(x, n);
    // GCN dense
    k_xw<<<(n + 31) / 32, 128>>>(gcn_w, n);
    // GCN gather + BN stats
    k_gcn_gs<<<(n * 32 + 255) / 256, 256>>>(gcn_b, n);
    // fused BN fold + output
    k_out<<<(n * 32 + 255) / 256, 256>>>(gamma, beta, lw, lb, out, n);
}

// round 13
// speedup vs baseline: 1.0713x; 1.0713x over previous
#include <cuda_runtime.h>

#define NMAX 50176
#define EMAX 800064
#define FEAT 32
#define HID  64

typedef unsigned long long ull;

// ---------------- scratch (device globals; no allocation allowed) ----------
__device__ __align__(16)  float2 g_cdeg[NMAX];   // (weighted in-sum, in-count)  keyed by col
__device__ __align__(16)  float2 g_rdeg[NMAX];   // (weighted out-sum, out-count) keyed by row
__device__ __align__(16)  float g_do_inv[NMAX];
__device__ __align__(16)  float g_di_inv[NMAX];
__device__ __align__(16)  float g_dis[NMAX];
__device__ __align__(16)  int   g_coff[NMAX + 1];
__device__ __align__(16)  int   g_roff[NMAX + 1];
__device__ __align__(16)  int   g_ccur[NMAX];
__device__ __align__(16)  int   g_rcur[NMAX];
__device__ __align__(16)  ull   g_cpay[EMAX];   // (f32 weight_out bits << 32) | src row r
__device__ __align__(16)  ull   g_rpay[EMAX];   // (f32 weight_in  bits << 32) | src col c
__device__ __align__(128) float g_P1o[NMAX * FEAT];
__device__ __align__(128) float g_P1i[NMAX * FEAT];
__device__ __align__(128) float g_P2o[NMAX * FEAT];
__device__ __align__(128) float g_P2i[NMAX * FEAT];
__device__ __align__(256) float g_xw[NMAX * HID];
__device__ __align__(256) float g_y[NMAX * HID];
__device__ __align__(16)  float g_Wcat[160 * 128];
__device__ __align__(16)  float g_bcat[128];
__device__ float g_S[HID];
__device__ float g_SS[HID];

// ---------------- helpers ----------------
__device__ __forceinline__ float sigm(float z) { return 1.0f / (1.0f + expf(-z)); }

__device__ __forceinline__ ull pk(float lo, float hi) {
    ull r; asm("mov.b64 %0, {%1, %2};" : "=l"(r) : "f"(lo), "f"(hi)); return r;
}
__device__ __forceinline__ float2 upk(ull v) {
    float2 r; asm("mov.b64 {%0, %1}, %2;" : "=f"(r.x), "=f"(r.y) : "l"(v)); return r;
}
__device__ __forceinline__ void fma2(ull& d, ull a, ull b) {
    asm("fma.rn.f32x2 %0, %1, %2, %0;" : "+l"(d) : "l"(a), "l"(b));
}
__device__ __forceinline__ void red2(float2* p, float a, float b) {
    asm volatile("red.global.add.v2.f32 [%0], {%1, %2};"
                 :: "l"(p), "f"(a), "f"(b) : "memory");
}

// ---------------- kernels ----------------

// zero accumulators + build fused 160x128 gate weight (one launch)
__global__ void k_init(const float* __restrict__ Wz, const float* __restrict__ Wh,
                       const float* __restrict__ bz, const float* __restrict__ bh, int n) {
    int i = blockIdx.x * blockDim.x + threadIdx.x;
    if (i < n) {
        g_cdeg[i] = make_float2(0.f, 0.f);
        g_rdeg[i] = make_float2(0.f, 0.f);
    }
    if (i < HID) { g_S[i] = 0.f; g_SS[i] = 0.f; }
    if (i < 160 * 128) {
        int k5 = i >> 7;
        int j  = i & 127;
        int b = k5 >> 5;
        int f = k5 & 31;
        const float* Wg = (j < 64) ? Wz : Wh;
        int jj = j & 63;
        float v;
        if (b == 0) {
            v = Wg[((0 * 3 + 0) * 96 + f) * 64 + jj] + Wg[((1 * 3 + 0) * 96 + f) * 64 + jj];
        } else {
            int d = (b <= 2) ? 0 : 1;
            int k = (b <= 2) ? b : (b - 2);
            v = Wg[((d * 3 + k) * 96 + f) * 64 + jj];
        }
        g_Wcat[i] = v;
    } else if (i < 160 * 128 + 128) {
        int j = i - 160 * 128;
        g_bcat[j] = (j < 64) ? bz[j] : bh[j - 64];
    }
}

// weighted degrees + CSR bin counts: one v2 reduction per edge per side
__global__ void k_deg(const int* __restrict__ row, const int* __restrict__ col,
                      const float* __restrict__ ew, int E) {
    int e = blockIdx.x * blockDim.x + threadIdx.x;
    if (e >= E) return;
    int r = row[e], c = col[e];
    float w = ew[e];
    red2(&g_rdeg[r], w, 1.0f);   // out-sum, out-count (row bins)
    red2(&g_cdeg[c], w, 1.0f);   // in-sum,  in-count  (col bins)
}

// single-phase offsets: each block sums preceding counts for its base, then
// per-tile inclusive scan -> off/cur. Col-array blocks also derive
// do_inv/di_inv/dis from the float2 degree accumulators.
__global__ void __launch_bounds__(256) k_off(int n, int NB) {
    int arr = (blockIdx.x >= NB) ? 1 : 0;
    int b = blockIdx.x - arr * NB;
    const float2* deg = arr ? g_rdeg : g_cdeg;
    int* off = arr ? g_roff : g_coff;
    int* cur = arr ? g_rcur : g_ccur;
    int t = threadIdx.x;
    int i = b * 256 + t;

    if (arr == 0 && i < n) {
        float so = g_rdeg[i].x;
        g_do_inv[i] = (so > 0.f) ? (1.0f / so) : 0.f;
        float si = g_cdeg[i].x;
        g_di_inv[i] = (si > 0.f) ? (1.0f / si) : 0.f;
        g_dis[i] = rsqrtf(g_cdeg[i].y + 1.0f);
    }

    // base = sum counts[0 .. b*256)
    int lim = b * 256;
    int part = 0;
    for (int q = t; q < lim; q += 256) part += __float2int_rn(deg[q].y);
#pragma unroll
    for (int o = 16; o > 0; o >>= 1) part += __shfl_down_sync(0xffffffffu, part, o);
    __shared__ int wred[8];
    if ((t & 31) == 0) wred[t >> 5] = part;
    __syncthreads();
    __shared__ int sbase;
    if (t == 0) {
        int s = 0;
#pragma unroll
        for (int q = 0; q < 8; q++) s += wred[q];
        sbase = s;
    }
    __shared__ int sm[256];
    int v = (i < n) ? __float2int_rn(deg[i].y) : 0;
    sm[t] = v;
    __syncthreads();
    for (int o = 1; o < 256; o <<= 1) {
        int u = (t >= o) ? sm[t - o] : 0;
        __syncthreads();
        sm[t] += u;
        __syncthreads();
    }
    int excl = sbase + sm[t] - v;
    if (i < n) { off[i] = excl; cur[i] = excl; }
    if (i == n - 1) off[n] = excl + v;
}

// place each edge payload into its dest bin (order within bin irrelevant)
__global__ void k_fill(const int* __restrict__ row, const int* __restrict__ col,
                       const float* __restrict__ ew, int E) {
    int e = blockIdx.x * blockDim.x + threadIdx.x;
    if (e >= E) return;
    int r = row[e], c = col[e];
    float w = ew[e];
    float wo = w * g_do_inv[r];
    float wi = w * g_di_inv[c];
    int p = atomicAdd(&g_ccur[c], 1);
    g_cpay[p] = ((ull)__float_as_uint(wo) << 32) | (unsigned)r;
    int p2 = atomicAdd(&g_rcur[r], 1);
    g_rpay[p2] = ((ull)__float_as_uint(wi) << 32) | (unsigned)c;
}

// diffusion hop as atomic-free gather, software-pipelined 4 edges/iteration.
// warp per (node,dir); lane = feature.
__global__ void k_spmm_g(const float* __restrict__ x, int hop, int n) {
    int t = blockIdx.x * blockDim.x + threadIdx.x;
    int wg = t >> 5;
    int lane = t & 31;
    if (wg >= 2 * n) return;
    int node = wg >> 1;
    int dir = wg & 1;
    const float* src;
    float* dst;
    const ull* pay;
    const int* off;
    if (dir == 0) { src = (hop == 1) ? x : g_P1o; dst = (hop == 1) ? g_P1o : g_P2o; pay = g_cpay; off = g_coff; }
    else          { src = (hop == 1) ? x : g_P1i; dst = (hop == 1) ? g_P1i : g_P2i; pay = g_rpay; off = g_roff; }
    int b0 = off[node], b1 = off[node + 1];
    float acc = 0.f;
    int i = b0;
    for (; i + 4 <= b1; i += 4) {
        ull p0 = pay[i];
        ull p1 = pay[i + 1];
        ull p2 = pay[i + 2];
        ull p3 = pay[i + 3];
        int s0 = (int)(unsigned)(p0 & 0xffffffffu);
        int s1 = (int)(unsigned)(p1 & 0xffffffffu);
        int s2 = (int)(unsigned)(p2 & 0xffffffffu);
        int s3 = (int)(unsigned)(p3 & 0xffffffffu);
        float v0 = src[s0 * FEAT + lane];
        float v1 = src[s1 * FEAT + lane];
        float v2 = src[s2 * FEAT + lane];
        float v3 = src[s3 * FEAT + lane];
        acc = fmaf(__uint_as_float((unsigned)(p0 >> 32)), v0, acc);
        acc = fmaf(__uint_as_float((unsigned)(p1 >> 32)), v1, acc);
        acc = fmaf(__uint_as_float((unsigned)(p2 >> 32)), v2, acc);
        acc = fmaf(__uint_as_float((unsigned)(p3 >> 32)), v3, acc);
    }
    for (; i < b1; i++) {
        ull p = pay[i];
        int s = (int)(unsigned)(p & 0xffffffffu);
        acc = fmaf(__uint_as_float((unsigned)(p >> 32)), src[s * FEAT + lane], acc);
    }
    dst[node * FEAT + lane] = acc;
}

// fused gate GEMM + GCN dense GEMM. Stage 1 (f32x2):
// [x|P1o|P2o|P1i|P2i](Nx160) @ Wcat(160x128)+bcat, H=(1-sigm(Zd))*tanh(Hd)
// staged into smem (H never touches global). Stage 2: xw = H @ gcn_w.
__global__ void __launch_bounds__(128) k_gatesxw(const float* __restrict__ x,
                                                 const float* __restrict__ gcn_w, int n) {
    __shared__ ull p2s[32 * 160];  // 40 KB; reused as H tile (32*64) in stage 2
    int tid = threadIdx.x;
    int n0 = blockIdx.x * 32;

    for (int idx = tid; idx < 32 * 160; idx += 128) {
        int m = idx / 160;
        int k = idx - m * 160;
        int node = n0 + m;
        float v = 0.f;
        if (node < n) {
            int b = k >> 5, f = k & 31;
            const float* src = (b == 0) ? x : (b == 1) ? g_P1o : (b == 2) ? g_P2o
                             : (b == 3) ? g_P1i : g_P2i;
            v = src[node * FEAT + f];
        }
        p2s[idx] = pk(v, v);
    }
    __syncthreads();

    int w = tid >> 5, j = tid & 31;
    int m0 = w * 8;

    ull acc[8][2];
    float4 bv = *reinterpret_cast<const float4*>(&g_bcat[4 * j]);
    ull b01 = pk(bv.x, bv.y), b23 = pk(bv.z, bv.w);
#pragma unroll
    for (int m = 0; m < 8; m++) { acc[m][0] = b01; acc[m][1] = b23; }

    const ulonglong2* Wm = reinterpret_cast<const ulonglong2*>(g_Wcat);
    for (int k = 0; k < 160; k++) {
        ulonglong2 wv = Wm[k * 32 + j];
#pragma unroll
        for (int m = 0; m < 8; m++) {
            ull pv = p2s[(m0 + m) * 160 + k];
            fma2(acc[m][0], wv.x, pv);
            fma2(acc[m][1], wv.y, pv);
        }
    }
    __syncthreads();   // all warps done reading p2s; safe to overwrite with H

    // epilogue: combine gate halves, stage H tile in smem (packed f32x2)
#pragma unroll
    for (int m = 0; m < 8; m++) {
        float2 a0 = upk(acc[m][0]);
        float2 a1 = upk(acc[m][1]);
        float p0 = __shfl_xor_sync(0xffffffffu, a0.x, 16);
        float p1 = __shfl_xor_sync(0xffffffffu, a0.y, 16);
        float p2 = __shfl_xor_sync(0xffffffffu, a1.x, 16);
        float p3 = __shfl_xor_sync(0xffffffffu, a1.y, 16);
        if (j < 16) {
            float h0 = (1.f - sigm(a0.x)) * tanhf(p0);
            float h1 = (1.f - sigm(a0.y)) * tanhf(p1);
            float h2 = (1.f - sigm(a1.x)) * tanhf(p2);
            float h3 = (1.f - sigm(a1.y)) * tanhf(p3);
            int base = (m0 + m) * 64 + 4 * j;
            p2s[base]     = pk(h0, h0);
            p2s[base + 1] = pk(h1, h1);
            p2s[base + 2] = pk(h2, h2);
            p2s[base + 3] = pk(h3, h3);
        }
    }
    __syncthreads();

    // stage 2: xw = H @ gcn_w (f32x2), lane j owns output cols 2j, 2j+1
    ull acc2[8];
#pragma unroll
    for (int m = 0; m < 8; m++) acc2[m] = 0ull;
    for (int k = 0; k < 64; k++) {
        ull wv = *reinterpret_cast<const ull*>(&gcn_w[k * 64 + 2 * j]);
#pragma unroll
        for (int m = 0; m < 8; m++) {
            fma2(acc2[m], wv, p2s[(m0 + m) * 64 + k]);
        }
    }
#pragma unroll
    for (int m = 0; m < 8; m++) {
        int node = n0 + m0 + m;
        if (node < n) {
            float2 a = upk(acc2[m]);
            *reinterpret_cast<float2*>(&g_xw[node * HID + 2 * j]) = a;
        }
    }
}

// GCN gather + fused BN statistics (atomic-free smem reduction).
// warp per node c; lane = channels lane, lane+32.
__global__ void __launch_bounds__(256) k_gcn_gs(const float* __restrict__ gcn_b, int n) {
    __shared__ float s1[8][64], s2[8][64];  // per-warp partials, 4 KB
    int tid = threadIdx.x;
    int warp = tid >> 5;
    int t = blockIdx.x * blockDim.x + tid;
    int c = t >> 5;
    int lane = t & 31;

    float r0 = 0.f, r1 = 0.f;
    if (c < n) {
        float dc = g_dis[c];
        float d2 = dc * dc;
        float a0 = fmaf(d2, g_xw[c * HID + lane],      gcn_b[lane]);
        float a1 = fmaf(d2, g_xw[c * HID + lane + 32], gcn_b[lane + 32]);
        int b0 = g_coff[c], b1 = g_coff[c + 1];
        int i = b0;
        for (; i + 2 <= b1; i += 2) {
            ull p0 = g_cpay[i];
            ull p1 = g_cpay[i + 1];
            int q0 = (int)(unsigned)(p0 & 0xffffffffu);
            int q1 = (int)(unsigned)(p1 & 0xffffffffu);
            float n0 = g_dis[q0] * dc;
            float n1 = g_dis[q1] * dc;
            float u00 = g_xw[q0 * HID + lane];
            float u01 = g_xw[q0 * HID + lane + 32];
            float u10 = g_xw[q1 * HID + lane];
            float u11 = g_xw[q1 * HID + lane + 32];
            a0 = fmaf(n0, u00, a0);
            a1 = fmaf(n0, u01, a1);
            a0 = fmaf(n1, u10, a0);
            a1 = fmaf(n1, u11, a1);
        }
        for (; i < b1; i++) {
            ull p = g_cpay[i];
            int r = (int)(unsigned)(p & 0xffffffffu);
            float nrm = g_dis[r] * dc;
            a0 = fmaf(nrm, g_xw[r * HID + lane],      a0);
            a1 = fmaf(nrm, g_xw[r * HID + lane + 32], a1);
        }
        g_y[c * HID + lane]      = a0;
        g_y[c * HID + lane + 32] = a1;
        r0 = fmaxf(a0, 0.f);
        r1 = fmaxf(a1, 0.f);
    }
    s1[warp][lane]      = r0;
    s1[warp][lane + 32] = r1;
    s2[warp][lane]      = r0 * r0;
    s2[warp][lane + 32] = r1 * r1;
    __syncthreads();
    if (tid < 64) {
        float a = 0.f, b = 0.f;
#pragma unroll
        for (int q = 0; q < 8; q++) { a += s1[q][tid]; b += s2[q][tid]; }
        atomicAdd(&g_S[tid],  a);
        atomicAdd(&g_SS[tid], b);
    }
}

// out[n] = dot(relu(y[n,:]), coef) + cnst, BN+linear fold computed inline.
__global__ void k_out(const float* __restrict__ gamma, const float* __restrict__ beta,
                      const float* __restrict__ lw, const float* __restrict__ lb,
                      float* __restrict__ out, int n) {
    int t = blockIdx.x * blockDim.x + threadIdx.x;
    int node = t >> 5;
    int j = t & 31;
    if (node >= n) return;
    float invn = 1.0f / (float)n;
    int j1 = j + 32;
    float m0 = g_S[j]  * invn,            m1 = g_S[j1] * invn;
    float v0 = g_SS[j] * invn - m0 * m0,  v1 = g_SS[j1] * invn - m1 * m1;
    float a0 = gamma[j]  * rsqrtf(v0 + 1e-5f);
    float a1 = gamma[j1] * rsqrtf(v1 + 1e-5f);
    float w0 = lw[j], w1 = lw[j1];
    float c0 = a0 * w0, c1 = a1 * w1;
    float part = (beta[j] - m0 * a0) * w0 + (beta[j1] - m1 * a1) * w1;
    float acc = fmaxf(g_y[node * HID + j],  0.f) * c0
              + fmaxf(g_y[node * HID + j1], 0.f) * c1
              + part;
#pragma unroll
    for (int o = 16; o > 0; o >>= 1) acc += __shfl_down_sync(0xffffffffu, acc, o);
    if (j == 0) out[node] = acc + lb[0];
}

// ---------------- launch ----------------
extern "C" void kernel_launch(void* const* d_in, const int* in_sizes, int n_in,
                              void* d_out, int out_size) {
    const float* x     = (const float*)d_in[0];
    const int*   ei    = (const int*)d_in[1];
    const float* ew    = (const float*)d_in[2];
    const float* Wz    = (const float*)d_in[3];
    const float* bz    = (const float*)d_in[4];
    const float* Wh    = (const float*)d_in[7];
    const float* bh    = (const float*)d_in[8];
    const float* gcn_w = (const float*)d_in[9];
    const float* gcn_b = (const float*)d_in[10];
    const float* gamma = (const float*)d_in[11];
    const float* beta  = (const float*)d_in[12];
    const float* lw    = (const float*)d_in[13];
    const float* lb    = (const float*)d_in[14];
    float* out = (float*)d_out;

    int n = in_sizes[0] / FEAT;
    int E = in_sizes[2];
    const int* row = ei;
    const int* col = ei + E;
    int NB = (n + 255) / 256;

    k_init<<<(n + 255) / 256, 256>>>(Wz, Wh, bz, bh, n);
    k_deg<<<(E + 255) / 256, 256>>>(row, col, ew, E);
    k_off<<<2 * NB, 256>>>(n, NB);
    k_fill<<<(E + 255) / 256, 256>>>(row, col, ew, E);
    k_spmm_g<<<(2 * n * 32 + 255) / 256, 256>>>(x, 1, n);
    k_spmm_g<<<(2 * n * 32 + 255) / 256, 256>>>(x, 2, n);
    k_gatesxw<<<(n + 31) / 32, 128>>>(x, gcn_w, n);
    k_gcn_gs<<<(n * 32 + 255) / 256, 256>>>(gcn_b, n);
    k_out<<<(n * 32 + 255) / 256, 256>>>(gamma, beta, lw, lb, out, n);
}

// round 15
// speedup vs baseline: 1.0996x; 1.0264x over previous
#include <cuda_runtime.h>
#include <cuda_fp16.h>

#define NMAX 50176
#define EMAX 800064
#define FEAT 32
#define HID  64

typedef unsigned long long ull;

// ---------------- scratch (device globals; no allocation allowed) ----------
__device__ __align__(16)  float2 g_cdeg[NMAX];   // (weighted in-sum, in-count)  keyed by col
__device__ __align__(16)  float2 g_rdeg[NMAX];   // (weighted out-sum, out-count) keyed by row
__device__ __align__(16)  float g_do_inv[NMAX];
__device__ __align__(16)  float g_di_inv[NMAX];
__device__ __align__(16)  float g_dis[NMAX];
__device__ __align__(16)  int   g_coff[NMAX + 1];
__device__ __align__(16)  int   g_roff[NMAX + 1];
__device__ __align__(16)  int   g_ccur[NMAX];
__device__ __align__(16)  int   g_rcur[NMAX];
__device__ __align__(16)  ull   g_cpay[EMAX];   // (f32 weight_out bits << 32) | src row r
__device__ __align__(16)  ull   g_rpay[EMAX];   // (f32 weight_in  bits << 32) | src col c
__device__ __align__(128) __half2 g_x16[NMAX * 16];    // x pre-converted, feature pairs
__device__ __align__(128) __half2 g_P1o[NMAX * 16];
__device__ __align__(128) __half2 g_P1i[NMAX * 16];
__device__ __align__(128) __half2 g_P2o[NMAX * 16];
__device__ __align__(128) __half2 g_P2i[NMAX * 16];
__device__ __align__(256) float   g_xw[NMAX * HID];    // fp32 (self term)
__device__ __align__(128) __half2 g_xw16[NMAX * 32];   // half copy (message gather)
__device__ __align__(256) float   g_y[NMAX * HID];
__device__ __align__(16)  float g_Wcat[160 * 128];
__device__ __align__(16)  float g_bcat[128];
__device__ float g_S[HID];
__device__ float g_SS[HID];

// ---------------- helpers ----------------
__device__ __forceinline__ float sigm(float z) { return 1.0f / (1.0f + expf(-z)); }

__device__ __forceinline__ ull pk(float lo, float hi) {
    ull r; asm("mov.b64 %0, {%1, %2};" : "=l"(r) : "f"(lo), "f"(hi)); return r;
}
__device__ __forceinline__ float2 upk(ull v) {
    float2 r; asm("mov.b64 {%0, %1}, %2;" : "=f"(r.x), "=f"(r.y) : "l"(v)); return r;
}
__device__ __forceinline__ void fma2(ull& d, ull a, ull b) {
    asm("fma.rn.f32x2 %0, %1, %2, %0;" : "+l"(d) : "l"(a), "l"(b));
}
__device__ __forceinline__ void red2(float2* p, float a, float b) {
    asm volatile("red.global.add.v2.f32 [%0], {%1, %2};"
                 :: "l"(p), "f"(a), "f"(b) : "memory");
}

// ---------------- kernels ----------------

// zero accumulators + build fused 160x128 gate weight (one launch)
__global__ void k_init(const float* __restrict__ Wz, const float* __restrict__ Wh,
                       const float* __restrict__ bz, const float* __restrict__ bh, int n) {
    int i = blockIdx.x * blockDim.x + threadIdx.x;
    if (i < n) {
        g_cdeg[i] = make_float2(0.f, 0.f);
        g_rdeg[i] = make_float2(0.f, 0.f);
    }
    if (i < HID) { g_S[i] = 0.f; g_SS[i] = 0.f; }
    if (i < 160 * 128) {
        int k5 = i >> 7;
        int j  = i & 127;
        int b = k5 >> 5;
        int f = k5 & 31;
        const float* Wg = (j < 64) ? Wz : Wh;
        int jj = j & 63;
        float v;
        if (b == 0) {
            v = Wg[((0 * 3 + 0) * 96 + f) * 64 + jj] + Wg[((1 * 3 + 0) * 96 + f) * 64 + jj];
        } else {
            int d = (b <= 2) ? 0 : 1;
            int k = (b <= 2) ? b : (b - 2);
            v = Wg[((d * 3 + k) * 96 + f) * 64 + jj];
        }
        g_Wcat[i] = v;
    } else if (i < 160 * 128 + 128) {
        int j = i - 160 * 128;
        g_bcat[j] = (j < 64) ? bz[j] : bh[j - 64];
    }
}

// weighted degrees + CSR bin counts: one v2 reduction per edge per side
__global__ void k_deg(const int* __restrict__ row, const int* __restrict__ col,
                      const float* __restrict__ ew, int E) {
    int e = blockIdx.x * blockDim.x + threadIdx.x;
    if (e >= E) return;
    int r = row[e], c = col[e];
    float w = ew[e];
    red2(&g_rdeg[r], w, 1.0f);
    red2(&g_cdeg[c], w, 1.0f);
}

// offsets + cursors + degree-inverse + x->half2 conversion
__global__ void __launch_bounds__(256) k_off(const float* __restrict__ x, int n, int NB) {
    int arr = (blockIdx.x >= NB) ? 1 : 0;
    int b = blockIdx.x - arr * NB;
    const float2* deg = arr ? g_rdeg : g_cdeg;
    int* off = arr ? g_roff : g_coff;
    int* cur = arr ? g_rcur : g_ccur;
    int t = threadIdx.x;
    int i = b * 256 + t;

    if (arr == 0 && i < n) {
        float so = g_rdeg[i].x;
        g_do_inv[i] = (so > 0.f) ? (1.0f / so) : 0.f;
        float si = g_cdeg[i].x;
        g_di_inv[i] = (si > 0.f) ? (1.0f / si) : 0.f;
        g_dis[i] = rsqrtf(g_cdeg[i].y + 1.0f);
        const float2* xr = reinterpret_cast<const float2*>(x + i * FEAT);
#pragma unroll
        for (int f = 0; f < 16; f++) {
            float2 v = xr[f];
            g_x16[i * 16 + f] = __floats2half2_rn(v.x, v.y);
        }
    }

    // base = sum counts[0 .. b*256)
    int lim = b * 256;
    int part = 0;
    for (int q = t; q < lim; q += 256) part += __float2int_rn(deg[q].y);
#pragma unroll
    for (int o = 16; o > 0; o >>= 1) part += __shfl_down_sync(0xffffffffu, part, o);
    __shared__ int wred[8];
    if ((t & 31) == 0) wred[t >> 5] = part;
    __syncthreads();
    __shared__ int sbase;
    if (t == 0) {
        int s = 0;
#pragma unroll
        for (int q = 0; q < 8; q++) s += wred[q];
        sbase = s;
    }
    __shared__ int sm[256];
    int v = (i < n) ? __float2int_rn(deg[i].y) : 0;
    sm[t] = v;
    __syncthreads();
    for (int o = 1; o < 256; o <<= 1) {
        int u = (t >= o) ? sm[t - o] : 0;
        __syncthreads();
        sm[t] += u;
        __syncthreads();
    }
    int excl = sbase + sm[t] - v;
    if (i < n) { off[i] = excl; cur[i] = excl; }
    if (i == n - 1) off[n] = excl + v;
}

// place each edge payload into its dest bin (order within bin irrelevant)
__global__ void k_fill(const int* __restrict__ row, const int* __restrict__ col,
                       const float* __restrict__ ew, int E) {
    int e = blockIdx.x * blockDim.x + threadIdx.x;
    if (e >= E) return;
    int r = row[e], c = col[e];
    float w = ew[e];
    float wo = w * g_do_inv[r];
    float wi = w * g_di_inv[c];
    int p = atomicAdd(&g_ccur[c], 1);
    g_cpay[p] = ((ull)__float_as_uint(wo) << 32) | (unsigned)r;
    int p2 = atomicAdd(&g_rcur[r], 1);
    g_rpay[p2] = ((ull)__float_as_uint(wi) << 32) | (unsigned)c;
}

// diffusion hop: half2 rows (64B), half-warp per edge (lane = feature pair),
// 4-edge software pipeline. warp per (node,dir).
__global__ void k_spmm_g(int hop, int n) {
    int t = blockIdx.x * blockDim.x + threadIdx.x;
    int wg = t >> 5;
    int lane = t & 31;
    if (wg >= 2 * n) return;
    int node = wg >> 1;
    int dir = wg & 1;
    int half = lane >> 4;    // 0: even edge, 1: odd edge
    int fp = lane & 15;      // feature pair
    const __half2* src;
    __half2* dst;
    const ull* pay;
    const int* off;
    if (dir == 0) { src = (hop == 1) ? g_x16 : g_P1o; dst = (hop == 1) ? g_P1o : g_P2o; pay = g_cpay; off = g_coff; }
    else          { src = (hop == 1) ? g_x16 : g_P1i; dst = (hop == 1) ? g_P1i : g_P2i; pay = g_rpay; off = g_roff; }
    int b0 = off[node], b1 = off[node + 1];
    float accx = 0.f, accy = 0.f;
    int i = b0;
    for (; i + 4 <= b1; i += 4) {
        ull pA = pay[i + half];
        ull pB = pay[i + 2 + half];
        int sA = (int)(unsigned)(pA & 0xffffffffu);
        int sB = (int)(unsigned)(pB & 0xffffffffu);
        float2 vA = __half22float2(src[sA * 16 + fp]);
        float2 vB = __half22float2(src[sB * 16 + fp]);
        float wA = __uint_as_float((unsigned)(pA >> 32));
        float wB = __uint_as_float((unsigned)(pB >> 32));
        accx = fmaf(wA, vA.x, accx);
        accy = fmaf(wA, vA.y, accy);
        accx = fmaf(wB, vB.x, accx);
        accy = fmaf(wB, vB.y, accy);
    }
    if (i + 2 <= b1) {
        ull p = pay[i + half];
        int s = (int)(unsigned)(p & 0xffffffffu);
        float2 v = __half22float2(src[s * 16 + fp]);
        float w = __uint_as_float((unsigned)(p >> 32));
        accx = fmaf(w, v.x, accx);
        accy = fmaf(w, v.y, accy);
        i += 2;
    }
    if (i < b1) {   // last single edge: even half only
        ull p = pay[i];
        int s = (int)(unsigned)(p & 0xffffffffu);
        float2 v = __half22float2(src[s * 16 + fp]);
        float w = __uint_as_float((unsigned)(p >> 32));
        if (half == 0) {
            accx = fmaf(w, v.x, accx);
            accy = fmaf(w, v.y, accy);
        }
    }
    // combine even/odd halves: lane 16+j has same fp == j
    accx += __shfl_xor_sync(0xffffffffu, accx, 16);
    accy += __shfl_xor_sync(0xffffffffu, accy, 16);
    if (half == 0) dst[node * 16 + fp] = __floats2half2_rn(accx, accy);
}

// fused gate GEMM + GCN dense GEMM (f32x2). Stage 1:
// [x|P1o|P2o|P1i|P2i](Nx160) @ Wcat(160x128)+bcat, H=(1-sigm(Zd))*tanh(Hd)
// staged in smem. Stage 2: xw = H @ gcn_w; written fp32 + half2 copy.
__global__ void __launch_bounds__(128) k_gatesxw(const float* __restrict__ x,
                                                 const float* __restrict__ gcn_w, int n) {
    __shared__ ull p2s[32 * 160];  // 40 KB; reused as H tile (32*64) in stage 2
    int tid = threadIdx.x;
    int n0 = blockIdx.x * 32;

    for (int idx = tid; idx < 32 * 160; idx += 128) {
        int m = idx / 160;
        int k = idx - m * 160;
        int node = n0 + m;
        float v = 0.f;
        if (node < n) {
            int b = k >> 5, f = k & 31;
            if (b == 0) {
                v = x[node * FEAT + f];
            } else {
                const __half2* s16 = (b == 1) ? g_P1o : (b == 2) ? g_P2o
                                   : (b == 3) ? g_P1i : g_P2i;
                __half2 h = s16[node * 16 + (f >> 1)];
                v = (f & 1) ? __high2float(h) : __low2float(h);
            }
        }
        p2s[idx] = pk(v, v);
    }
    __syncthreads();

    int w = tid >> 5, j = tid & 31;
    int m0 = w * 8;

    ull acc[8][2];
    float4 bv = *reinterpret_cast<const float4*>(&g_bcat[4 * j]);
    ull b01 = pk(bv.x, bv.y), b23 = pk(bv.z, bv.w);
#pragma unroll
    for (int m = 0; m < 8; m++) { acc[m][0] = b01; acc[m][1] = b23; }

    const ulonglong2* Wm = reinterpret_cast<const ulonglong2*>(g_Wcat);
    for (int k = 0; k < 160; k++) {
        ulonglong2 wv = Wm[k * 32 + j];
#pragma unroll
        for (int m = 0; m < 8; m++) {
            ull pv = p2s[(m0 + m) * 160 + k];
            fma2(acc[m][0], wv.x, pv);
            fma2(acc[m][1], wv.y, pv);
        }
    }
    __syncthreads();

#pragma unroll
    for (int m = 0; m < 8; m++) {
        float2 a0 = upk(acc[m][0]);
        float2 a1 = upk(acc[m][1]);
        float p0 = __shfl_xor_sync(0xffffffffu, a0.x, 16);
        float p1 = __shfl_xor_sync(0xffffffffu, a0.y, 16);
        float p2 = __shfl_xor_sync(0xffffffffu, a1.x, 16);
        float p3 = __shfl_xor_sync(0xffffffffu, a1.y, 16);
        if (j < 16) {
            float h0 = (1.f - sigm(a0.x)) * tanhf(p0);
            float h1 = (1.f - sigm(a0.y)) * tanhf(p1);
            float h2 = (1.f - sigm(a1.x)) * tanhf(p2);
            float h3 = (1.f - sigm(a1.y)) * tanhf(p3);
            int base = (m0 + m) * 64 + 4 * j;
            p2s[base]     = pk(h0, h0);
            p2s[base + 1] = pk(h1, h1);
            p2s[base + 2] = pk(h2, h2);
            p2s[base + 3] = pk(h3, h3);
        }
    }
    __syncthreads();

    ull acc2[8];
#pragma unroll
    for (int m = 0; m < 8; m++) acc2[m] = 0ull;
    for (int k = 0; k < 64; k++) {
        ull wv = *reinterpret_cast<const ull*>(&gcn_w[k * 64 + 2 * j]);
#pragma unroll
        for (int m = 0; m < 8; m++) {
            fma2(acc2[m], wv, p2s[(m0 + m) * 64 + k]);
        }
    }
#pragma unroll
    for (int m = 0; m < 8; m++) {
        int node = n0 + m0 + m;
        if (node < n) {
            float2 a = upk(acc2[m]);
            *reinterpret_cast<float2*>(&g_xw[node * HID + 2 * j]) = a;
            g_xw16[node * 32 + j] = __floats2half2_rn(a.x, a.y);
        }
    }
}

// GCN gather + fused BN statistics. warp per node c; lane = feature pair (2l,2l+1).
// Messages gathered from half2 xw copy (128B rows); self term from fp32 xw.
__global__ void __launch_bounds__(256) k_gcn_gs(const float* __restrict__ gcn_b, int n) {
    __shared__ float s1[8][64], s2[8][64];
    int tid = threadIdx.x;
    int warp = tid >> 5;
    int t = blockIdx.x * blockDim.x + tid;
    int c = t >> 5;
    int lane = t & 31;

    float r0 = 0.f, r1 = 0.f;
    if (c < n) {
        float dc = g_dis[c];
        float d2 = dc * dc;
        float2 selfv = *reinterpret_cast<const float2*>(&g_xw[c * HID + 2 * lane]);
        float2 gb = *reinterpret_cast<const float2*>(&gcn_b[2 * lane]);
        float a0 = fmaf(d2, selfv.x, gb.x);
        float a1 = fmaf(d2, selfv.y, gb.y);
        int b0 = g_coff[c], b1 = g_coff[c + 1];
        int i = b0;
        for (; i + 2 <= b1; i += 2) {
            ull p0 = g_cpay[i];
            ull p1 = g_cpay[i + 1];
            int q0 = (int)(unsigned)(p0 & 0xffffffffu);
            int q1 = (int)(unsigned)(p1 & 0xffffffffu);
            float n0 = g_dis[q0] * dc;
            float n1 = g_dis[q1] * dc;
            float2 v0 = __half22float2(g_xw16[q0 * 32 + lane]);
            float2 v1 = __half22float2(g_xw16[q1 * 32 + lane]);
            a0 = fmaf(n0, v0.x, a0);
            a1 = fmaf(n0, v0.y, a1);
            a0 = fmaf(n1, v1.x, a0);
            a1 = fmaf(n1, v1.y, a1);
        }
        for (; i < b1; i++) {
            ull p = g_cpay[i];
            int r = (int)(unsigned)(p & 0xffffffffu);
            float nrm = g_dis[r] * dc;
            float2 v = __half22float2(g_xw16[r * 32 + lane]);
            a0 = fmaf(nrm, v.x, a0);
            a1 = fmaf(nrm, v.y, a1);
        }
        *reinterpret_cast<float2*>(&g_y[c * HID + 2 * lane]) = make_float2(a0, a1);
        r0 = fmaxf(a0, 0.f);
        r1 = fmaxf(a1, 0.f);
    }
    *reinterpret_cast<float2*>(&s1[warp][2 * lane]) = make_float2(r0, r1);
    *reinterpret_cast<float2*>(&s2[warp][2 * lane]) = make_float2(r0 * r0, r1 * r1);
    __syncthreads();
    if (tid < 64) {
        float a = 0.f, b = 0.f;
#pragma unroll
        for (int q = 0; q < 8; q++) { a += s1[q][tid]; b += s2[q][tid]; }
        atomicAdd(&g_S[tid],  a);
        atomicAdd(&g_SS[tid], b);
    }
}

// out[n] = dot(relu(y[n,:]), coef) + cnst; lane = feature pair (2j,2j+1).
__global__ void k_out(const float* __restrict__ gamma, const float* __restrict__ beta,
                      const float* __restrict__ lw, const float* __restrict__ lb,
                      float* __restrict__ out, int n) {
    int t = blockIdx.x * blockDim.x + threadIdx.x;
    int node = t >> 5;
    int j = t & 31;
    if (node >= n) return;
    float invn = 1.0f / (float)n;
    int c0i = 2 * j, c1i = 2 * j + 1;
    float m0 = g_S[c0i]  * invn,            m1 = g_S[c1i] * invn;
    float v0 = g_SS[c0i] * invn - m0 * m0,  v1 = g_SS[c1i] * invn - m1 * m1;
    float a0 = gamma[c0i] * rsqrtf(v0 + 1e-5f);
    float a1 = gamma[c1i] * rsqrtf(v1 + 1e-5f);
    float w0 = lw[c0i], w1 = lw[c1i];
    float c0 = a0 * w0, c1 = a1 * w1;
    float part = (beta[c0i] - m0 * a0) * w0 + (beta[c1i] - m1 * a1) * w1;
    float2 yv = *reinterpret_cast<const float2*>(&g_y[node * HID + 2 * j]);
    float acc = fmaxf(yv.x, 0.f) * c0 + fmaxf(yv.y, 0.f) * c1 + part;
#pragma unroll
    for (int o = 16; o > 0; o >>= 1) acc += __shfl_down_sync(0xffffffffu, acc, o);
    if (j == 0) out[node] = acc + lb[0];
}

// ---------------- launch ----------------
extern "C" void kernel_launch(void* const* d_in, const int* in_sizes, int n_in,
                              void* d_out, int out_size) {
    const float* x     = (const float*)d_in[0];
    const int*   ei    = (const int*)d_in[1];
    const float* ew    = (const float*)d_in[2];
    const float* Wz    = (const float*)d_in[3];
    const float* bz    = (const float*)d_in[4];
    const float* Wh    = (const float*)d_in[7];
    const float* bh    = (const float*)d_in[8];
    const float* gcn_w = (const float*)d_in[9];
    const float* gcn_b = (const float*)d_in[10];
    const float* gamma = (const float*)d_in[11];
    const float* beta  = (const float*)d_in[12];
    const float* lw    = (const float*)d_in[13];
    const float* lb    = (const float*)d_in[14];
    float* out = (float*)d_out;

    int n = in_sizes[0] / FEAT;
    int E = in_sizes[2];
    const int* row = ei;
    const int* col = ei + E;
    int NB = (n + 255) / 256;

    k_init<<<(n + 255) / 256, 256>>>(Wz, Wh, bz, bh, n);
    k_deg<<<(E + 255) / 256, 256>>>(row, col, ew, E);
    k_off<<<2 * NB, 256>>>(x, n, NB);
    k_fill<<<(E + 255) / 256, 256>>>(row, col, ew, E);
    k_spmm_g<<<(2 * n * 32 + 255) / 256, 256>>>(1, n);
    k_spmm_g<<<(2 * n * 32 + 255) / 256, 256>>>(2, n);
    k_gatesxw<<<(n + 31) / 32, 128>>>(x, gcn_w, n);
    k_gcn_gs<<<(n * 32 + 255) / 256, 256>>>(gcn_b, n);
    k_out<<<(n * 32 + 255) / 256, 256>>>(gamma, beta, lw, lb, out, n);
}